// round 7
// baseline (speedup 1.0000x reference)
#include <cuda_runtime.h>
#include <cuda_bf16.h>
#include <cuda_fp16.h>
#include <cstdint>

#define N_NODES  50000
#define N_EDGES  800000
#define IN_F     512
#define OUT_F    96
#define ALPHA    0.1f
#define ITERS    10
#define SCAN_BLK 512
#define NBLK     ((N_NODES + SCAN_BLK - 1) / SCAN_BLK)   // 98

// ---- device-global scratch (allocation-free per harness rules) -------------
__device__ __align__(16) __half g_hsup[(size_t)N_NODES * OUT_F];
__device__ __align__(16) __half g_hA[(size_t)N_NODES * OUT_F];
__device__ __align__(16) __half g_hB[(size_t)N_NODES * OUT_F];
__device__ int    g_rowptr[N_NODES + 1];
__device__ int    g_cursor[N_NODES];
__device__ int    g_deg[N_NODES];
__device__ int    g_blocksum[NBLK];
__device__ int    g_blockoff[NBLK];
__device__ __align__(16) int2 g_epack[N_EDGES];           // {src, bits(0.9*val)}
// W split into bf16 hi/lo, transposed to [OUT_F][IN_F]
__device__ __align__(16) __nv_bfloat16 g_WhiT[(size_t)OUT_F * IN_F];
__device__ __align__(16) __nv_bfloat16 g_WloT[(size_t)OUT_F * IN_F];

// ---------------------------------------------------------------------------
// helpers for tensor-core GEMM
// ---------------------------------------------------------------------------
__device__ __forceinline__ uint32_t smem_u32(const void* p) {
    uint32_t a;
    asm("{ .reg .u64 t; cvta.to.shared.u64 t, %1; cvt.u32.u64 %0, t; }"
        : "=r"(a) : "l"(p));
    return a;
}

__device__ __forceinline__ void ldsm_x4(uint32_t* r, uint32_t addr) {
    asm volatile("ldmatrix.sync.aligned.m8n8.x4.shared.b16 {%0,%1,%2,%3}, [%4];"
                 : "=r"(r[0]), "=r"(r[1]), "=r"(r[2]), "=r"(r[3]) : "r"(addr));
}

__device__ __forceinline__ void mma_bf16(float* d, const uint32_t* a,
                                         uint32_t b0, uint32_t b1) {
    asm volatile("mma.sync.aligned.m16n8k16.row.col.f32.bf16.bf16.f32 "
                 "{%0,%1,%2,%3}, {%4,%5,%6,%7}, {%8,%9}, {%0,%1,%2,%3};"
                 : "+f"(d[0]), "+f"(d[1]), "+f"(d[2]), "+f"(d[3])
                 : "r"(a[0]), "r"(a[1]), "r"(a[2]), "r"(a[3]),
                   "r"(b0), "r"(b1));
}

// ---------------------------------------------------------------------------
// W preconvert: split fp32 W[512,96] into bf16 hi/lo, transposed [96][512]
// ---------------------------------------------------------------------------
__global__ void wconv_kernel(const float* __restrict__ W) {
    int i = blockIdx.x * blockDim.x + threadIdx.x;
    if (i < IN_F * OUT_F) {
        int k = i / OUT_F, n = i % OUT_F;
        float w = W[i];
        __nv_bfloat16 hi = __float2bfloat16_rn(w);
        float lo = w - __bfloat162float(hi);
        g_WhiT[(size_t)n * IN_F + k] = hi;
        g_WloT[(size_t)n * IN_F + k] = __float2bfloat16_rn(lo);
    }
}

// ---------------------------------------------------------------------------
// GEMM via mma.sync bf16 split: hsup = fp16(X @ W)
// ---------------------------------------------------------------------------
#define SMS 144   // bytes per smem row
#define A_HI_OFF 0
#define A_LO_OFF 18432         // 128*144
#define B_HI_OFF 36864
#define B_LO_OFF 50688
#define GEMM_SMEM 64512

__global__ __launch_bounds__(256, 2) void gemm_mma_kernel(
    const float* __restrict__ X, __half* __restrict__ hout)
{
    extern __shared__ char sm[];
    char* As_hi = sm + A_HI_OFF;
    char* As_lo = sm + A_LO_OFF;
    char* Bs_hi = sm + B_HI_OFF;
    char* Bs_lo = sm + B_LO_OFF;

    const int tid  = threadIdx.x;
    const int lane = tid & 31;
    const int wid  = tid >> 5;
    const int wm   = wid >> 1;
    const int wn   = wid & 1;
    const int ctaM = blockIdx.x * 128;

    float acc[2][6][4];
#pragma unroll
    for (int mt = 0; mt < 2; ++mt)
#pragma unroll
        for (int nt = 0; nt < 6; ++nt)
#pragma unroll
            for (int r = 0; r < 4; ++r) acc[mt][nt][r] = 0.0f;

    const uint32_t a_hi = smem_u32(As_hi);
    const uint32_t a_lo = smem_u32(As_lo);
    const uint32_t b_hi = smem_u32(Bs_hi);
    const uint32_t b_lo = smem_u32(Bs_lo);

    const int a_row = ((lane >> 3) & 1) * 8 + (lane & 7);
    const int a_kh  = lane >> 4;
    const int b_row = ((lane >> 4) & 1) * 8 + (lane & 7);
    const int b_kh  = (lane >> 3) & 1;

    for (int k0 = 0; k0 < IN_F; k0 += 64) {
#pragma unroll
        for (int j = 0; j < 8; ++j) {
            int i   = tid + j * 256;
            int row = i >> 4;
            int kg  = i & 15;
            int grow = ctaM + row;
            if (grow >= N_NODES) grow = N_NODES - 1;
            float4 v = *reinterpret_cast<const float4*>(
                X + (size_t)grow * IN_F + k0 + kg * 4);
            __nv_bfloat16 h0 = __float2bfloat16_rn(v.x);
            __nv_bfloat16 h1 = __float2bfloat16_rn(v.y);
            __nv_bfloat16 h2 = __float2bfloat16_rn(v.z);
            __nv_bfloat16 h3 = __float2bfloat16_rn(v.w);
            char* ph = As_hi + row * SMS + kg * 8;
            *reinterpret_cast<__nv_bfloat162*>(ph)     = __halves2bfloat162(h0, h1);
            *reinterpret_cast<__nv_bfloat162*>(ph + 4) = __halves2bfloat162(h2, h3);
            __nv_bfloat16 l0 = __float2bfloat16_rn(v.x - __bfloat162float(h0));
            __nv_bfloat16 l1 = __float2bfloat16_rn(v.y - __bfloat162float(h1));
            __nv_bfloat16 l2 = __float2bfloat16_rn(v.z - __bfloat162float(h2));
            __nv_bfloat16 l3 = __float2bfloat16_rn(v.w - __bfloat162float(h3));
            char* pl = As_lo + row * SMS + kg * 8;
            *reinterpret_cast<__nv_bfloat162*>(pl)     = __halves2bfloat162(l0, l1);
            *reinterpret_cast<__nv_bfloat162*>(pl + 4) = __halves2bfloat162(l2, l3);
        }
#pragma unroll
        for (int j = 0; j < 3; ++j) {
            int i   = tid + j * 256;
            int row = i >> 3;
            int kg  = i & 7;
            size_t goff = ((size_t)row * IN_F + k0) * 2 + kg * 16;
            *reinterpret_cast<uint4*>(Bs_hi + row * SMS + kg * 16) =
                *reinterpret_cast<const uint4*>(
                    reinterpret_cast<const char*>(g_WhiT) + goff);
            *reinterpret_cast<uint4*>(Bs_lo + row * SMS + kg * 16) =
                *reinterpret_cast<const uint4*>(
                    reinterpret_cast<const char*>(g_WloT) + goff);
        }
        __syncthreads();

#pragma unroll
        for (int ks = 0; ks < 4; ++ks) {
            uint32_t Ah[2][4], Al[2][4];
#pragma unroll
            for (int mt = 0; mt < 2; ++mt) {
                uint32_t off = (uint32_t)((wm * 32 + mt * 16 + a_row) * SMS
                                          + ks * 32 + a_kh * 16);
                ldsm_x4(Ah[mt], a_hi + off);
                ldsm_x4(Al[mt], a_lo + off);
            }
            uint32_t Bh[3][4], Bl[3][4];
#pragma unroll
            for (int np = 0; np < 3; ++np) {
                uint32_t off = (uint32_t)((wn * 48 + np * 16 + b_row) * SMS
                                          + ks * 32 + b_kh * 16);
                ldsm_x4(Bh[np], b_hi + off);
                ldsm_x4(Bl[np], b_lo + off);
            }
#pragma unroll
            for (int mt = 0; mt < 2; ++mt)
#pragma unroll
                for (int nt = 0; nt < 6; ++nt) {
                    uint32_t bh0 = Bh[nt >> 1][(nt & 1) * 2];
                    uint32_t bh1 = Bh[nt >> 1][(nt & 1) * 2 + 1];
                    uint32_t bl0 = Bl[nt >> 1][(nt & 1) * 2];
                    uint32_t bl1 = Bl[nt >> 1][(nt & 1) * 2 + 1];
                    mma_bf16(acc[mt][nt], Ah[mt], bh0, bh1);
                    mma_bf16(acc[mt][nt], Ah[mt], bl0, bl1);
                    mma_bf16(acc[mt][nt], Al[mt], bh0, bh1);
                }
        }
        __syncthreads();
    }

#pragma unroll
    for (int mt = 0; mt < 2; ++mt) {
        int row0 = ctaM + wm * 32 + mt * 16 + (lane >> 2);
#pragma unroll
        for (int nt = 0; nt < 6; ++nt) {
            int col = wn * 48 + nt * 8 + (lane & 3) * 2;
            if (row0 < N_NODES)
                *reinterpret_cast<__half2*>(hout + (size_t)row0 * OUT_F + col) =
                    __floats2half2_rn(acc[mt][nt][0], acc[mt][nt][1]);
            int row1 = row0 + 8;
            if (row1 < N_NODES)
                *reinterpret_cast<__half2*>(hout + (size_t)row1 * OUT_F + col) =
                    __floats2half2_rn(acc[mt][nt][2], acc[mt][nt][3]);
        }
    }
}

// ---------------------------------------------------------------------------
// CSR build: histogram -> scan -> fill (packed src+val)
// ---------------------------------------------------------------------------
__global__ void zero_deg_kernel() {
    int i = blockIdx.x * blockDim.x + threadIdx.x;
    if (i < N_NODES) g_deg[i] = 0;
}

__global__ void hist_kernel(const int* __restrict__ dst) {
    int i = blockIdx.x * blockDim.x + threadIdx.x;
    if (i < N_EDGES) atomicAdd(&g_deg[dst[i]], 1);
}

__global__ __launch_bounds__(SCAN_BLK) void scan1_kernel() {
    __shared__ int sh[SCAN_BLK];
    int t = threadIdx.x;
    int gi = blockIdx.x * SCAN_BLK + t;
    int v = (gi < N_NODES) ? g_deg[gi] : 0;
    sh[t] = v;
    __syncthreads();
#pragma unroll
    for (int off = 1; off < SCAN_BLK; off <<= 1) {
        int x = (t >= off) ? sh[t - off] : 0;
        __syncthreads();
        sh[t] += x;
        __syncthreads();
    }
    if (gi < N_NODES) g_rowptr[gi] = sh[t] - v;
    if (t == SCAN_BLK - 1) g_blocksum[blockIdx.x] = sh[t];
}

__global__ __launch_bounds__(128) void scan2_kernel() {
    __shared__ int sh[128];
    int t = threadIdx.x;
    int v = (t < NBLK) ? g_blocksum[t] : 0;
    sh[t] = v;
    __syncthreads();
#pragma unroll
    for (int off = 1; off < 128; off <<= 1) {
        int x = (t >= off) ? sh[t - off] : 0;
        __syncthreads();
        sh[t] += x;
        __syncthreads();
    }
    if (t < NBLK) g_blockoff[t] = sh[t] - v;
}

__global__ void scan3_kernel() {
    int i = blockIdx.x * blockDim.x + threadIdx.x;
    if (i < N_NODES) {
        int r = g_rowptr[i] + g_blockoff[i / SCAN_BLK];
        g_rowptr[i] = r;
        g_cursor[i] = r;
    }
    if (i == 0) g_rowptr[N_NODES] = N_EDGES;
}

__global__ void fill_kernel(const int* __restrict__ src,
                            const int* __restrict__ dst,
                            const float* __restrict__ val) {
    int i = blockIdx.x * blockDim.x + threadIdx.x;
    if (i < N_EDGES) {
        int pos = atomicAdd(&g_cursor[dst[i]], 1);
        g_epack[pos] = make_int2(src[i],
                                 __float_as_int(val[i] * (1.0f - ALPHA)));
    }
}

// ---------------------------------------------------------------------------
// SpMM: 2 destination nodes per warp, fused interleaved edge loop (2 chains),
// fp16 state with __half2 gathers. Lane l owns feature pair l (feats 2l,2l+1);
// lanes 0-15 also own pair 32+l.
// Out-of-range edge slots clamp to the row's first edge with v=0 (L2-hot, safe).
// ---------------------------------------------------------------------------
__device__ __forceinline__ int2 fetch_edge(int i, int end, int safe) {
    int idx = (i < end) ? i : safe;
    int2 e = __ldg(&g_epack[idx]);
    if (i >= end) e.y = 0;
    return e;
}

template <int RELU_IN, int FINAL>
__global__ __launch_bounds__(256) void spmm_kernel(
    const __half* __restrict__ cur, const __half* __restrict__ sup,
    __half* __restrict__ outh, float* __restrict__ outf)
{
    const int warp = (blockIdx.x * 256 + threadIdx.x) >> 5;
    const int lane = threadIdx.x & 31;
    const int n0 = warp * 2;
    if (n0 >= N_NODES) return;
    const int n1 = n0 + 1;                      // N_NODES even -> always valid
    const bool hi = lane < 16;
    const __half2 z2 = __float2half2_rn(0.0f);

    const int beg0 = __ldg(&g_rowptr[n0]);
    const int end0 = __ldg(&g_rowptr[n0 + 1]);
    const int end1 = __ldg(&g_rowptr[n1 + 1]);
    const int beg1 = end0;
    const int sb0 = min(beg0, N_EDGES - 1);
    const int sb1 = min(beg1, N_EDGES - 1);

    float2 A0 = make_float2(0.f, 0.f), A1 = make_float2(0.f, 0.f);
    float2 B0 = make_float2(0.f, 0.f), B1 = make_float2(0.f, 0.f);

#define GATHER(E, X0, X1)                                                     \
    {                                                                         \
        const __half2* r =                                                    \
            reinterpret_cast<const __half2*>(cur + (size_t)(E).x * OUT_F);    \
        float v = __int_as_float((E).y);                                      \
        __half2 p0 = __ldg(r + lane);                                         \
        __half2 p1 = hi ? __ldg(r + 32 + lane) : z2;                          \
        if (RELU_IN) { p0 = __hmax2(p0, z2); p1 = __hmax2(p1, z2); }          \
        float2 f0 = __half22float2(p0);                                       \
        float2 f1 = __half22float2(p1);                                       \
        X0.x = fmaf(v, f0.x, X0.x); X0.y = fmaf(v, f0.y, X0.y);               \
        X1.x = fmaf(v, f1.x, X1.x); X1.y = fmaf(v, f1.y, X1.y);               \
    }

    const int d0 = end0 - beg0;
    const int d1 = end1 - beg1;
    const int m  = max(d0, d1);

    for (int k = 0; k < m; k += 2) {
        int2 ea0 = fetch_edge(beg0 + k,     end0, sb0);
        int2 eb0 = fetch_edge(beg1 + k,     end1, sb1);
        int2 ea1 = fetch_edge(beg0 + k + 1, end0, sb0);
        int2 eb1 = fetch_edge(beg1 + k + 1, end1, sb1);
        GATHER(ea0, A0, A1);
        GATHER(eb0, B0, B1);
        GATHER(ea1, A0, A1);
        GATHER(eb1, B0, B1);
    }
#undef GATHER

    // residual + store, node0 then node1
    const __half2* sp0 = reinterpret_cast<const __half2*>(sup + (size_t)n0 * OUT_F);
    const __half2* sp1 = reinterpret_cast<const __half2*>(sup + (size_t)n1 * OUT_F);
    float2 s00 = __half22float2(__ldg(sp0 + lane));
    float2 s01 = hi ? __half22float2(__ldg(sp0 + 32 + lane)) : make_float2(0.f, 0.f);
    float2 s10 = __half22float2(__ldg(sp1 + lane));
    float2 s11 = hi ? __half22float2(__ldg(sp1 + 32 + lane)) : make_float2(0.f, 0.f);

    float a00 = fmaf(ALPHA, s00.x, A0.x), a01 = fmaf(ALPHA, s00.y, A0.y);
    float a10 = fmaf(ALPHA, s01.x, A1.x), a11 = fmaf(ALPHA, s01.y, A1.y);
    float b00 = fmaf(ALPHA, s10.x, B0.x), b01 = fmaf(ALPHA, s10.y, B0.y);
    float b10 = fmaf(ALPHA, s11.x, B1.x), b11 = fmaf(ALPHA, s11.y, B1.y);

    if (FINAL) {
        a00 = fmaxf(a00, 0.f); a01 = fmaxf(a01, 0.f);
        a10 = fmaxf(a10, 0.f); a11 = fmaxf(a11, 0.f);
        b00 = fmaxf(b00, 0.f); b01 = fmaxf(b01, 0.f);
        b10 = fmaxf(b10, 0.f); b11 = fmaxf(b11, 0.f);
        float* o0 = outf + (size_t)n0 * OUT_F;
        float* o1 = outf + (size_t)n1 * OUT_F;
        *reinterpret_cast<float2*>(o0 + 2 * lane) = make_float2(a00, a01);
        *reinterpret_cast<float2*>(o1 + 2 * lane) = make_float2(b00, b01);
        if (hi) {
            *reinterpret_cast<float2*>(o0 + 64 + 2 * lane) = make_float2(a10, a11);
            *reinterpret_cast<float2*>(o1 + 64 + 2 * lane) = make_float2(b10, b11);
        }
    } else {
        __half2* o0 = reinterpret_cast<__half2*>(outh + (size_t)n0 * OUT_F);
        __half2* o1 = reinterpret_cast<__half2*>(outh + (size_t)n1 * OUT_F);
        o0[lane] = __floats2half2_rn(a00, a01);
        o1[lane] = __floats2half2_rn(b00, b01);
        if (hi) {
            o0[32 + lane] = __floats2half2_rn(a10, a11);
            o1[32 + lane] = __floats2half2_rn(b10, b11);
        }
    }
}

// ---------------------------------------------------------------------------
extern "C" void kernel_launch(void* const* d_in, const int* in_sizes, int n_in,
                              void* d_out, int out_size)
{
    const float* x    = (const float*)d_in[0];
    const float* w    = (const float*)d_in[1];
    const int*   src  = (const int*)d_in[2];
    const int*   dst  = (const int*)d_in[3];
    const float* val  = (const float*)d_in[4];
    float*       out  = (float*)d_out;

    __half *hsup, *hA, *hB;
    cudaGetSymbolAddress((void**)&hsup, g_hsup);
    cudaGetSymbolAddress((void**)&hA,   g_hA);
    cudaGetSymbolAddress((void**)&hB,   g_hB);

    // 1) GEMM (split-bf16 tensor core), writes fp16 support
    cudaFuncSetAttribute(gemm_mma_kernel,
                         cudaFuncAttributeMaxDynamicSharedMemorySize, GEMM_SMEM);
    wconv_kernel<<<(IN_F * OUT_F + 255) / 256, 256>>>(w);
    gemm_mma_kernel<<<(N_NODES + 127) / 128, 256, GEMM_SMEM>>>(x, hsup);

    // 2) CSR build (dst-sorted adjacency, packed src+val)
    zero_deg_kernel<<<(N_NODES + 255) / 256, 256>>>();
    hist_kernel<<<(N_EDGES + 255) / 256, 256>>>(dst);
    scan1_kernel<<<NBLK, SCAN_BLK>>>();
    scan2_kernel<<<1, 128>>>();
    scan3_kernel<<<(N_NODES + 255) / 256, 256>>>();
    fill_kernel<<<(N_EDGES + 255) / 256, 256>>>(src, dst, val);

    // 3) 10 propagation iterations, 2 nodes/warp, fp16 state
    const int nWarps = N_NODES / 2;                       // 25000
    const int spmmBlocks = (nWarps * 32 + 255) / 256;     // 3125
    const __half* cur = hsup;
    for (int it = 0; it < ITERS; ++it) {
        __half* nxt = (it & 1) ? hB : hA;
        if (it == 0)
            spmm_kernel<0, 0><<<spmmBlocks, 256>>>(cur, hsup, nxt, nullptr);
        else if (it == ITERS - 1)
            spmm_kernel<1, 1><<<spmmBlocks, 256>>>(cur, hsup, nullptr, out);
        else
            spmm_kernel<1, 0><<<spmmBlocks, 256>>>(cur, hsup, nxt, nullptr);
        cur = nxt;
    }
}

// round 8
// speedup vs baseline: 1.5426x; 1.5426x over previous
#include <cuda_runtime.h>
#include <cuda_bf16.h>
#include <cstdint>

#define N_NODES  50000
#define N_EDGES  800000
#define IN_F     512
#define OUT_F    96
#define ALPHA    0.1f
#define ITERS    10
#define SCAN_BLK 512
#define NBLK     ((N_NODES + SCAN_BLK - 1) / SCAN_BLK)   // 98

// ---- device-global scratch (allocation-free per harness rules) -------------
__device__ float g_support[(size_t)N_NODES * OUT_F];
__device__ float g_bufA[(size_t)N_NODES * OUT_F];
__device__ float g_bufB[(size_t)N_NODES * OUT_F];
__device__ int   g_rowptr[N_NODES + 1];
__device__ int   g_cursor[N_NODES];
__device__ int   g_deg[N_NODES];
__device__ int   g_blocksum[NBLK];
__device__ int   g_blockoff[NBLK];
__device__ int   g_esrc[N_EDGES];
__device__ float g_eval[N_EDGES];
// W split into bf16 hi/lo, transposed to [OUT_F][IN_F]
__device__ __align__(16) __nv_bfloat16 g_WhiT[(size_t)OUT_F * IN_F];
__device__ __align__(16) __nv_bfloat16 g_WloT[(size_t)OUT_F * IN_F];

// ---------------------------------------------------------------------------
// helpers for tensor-core GEMM
// ---------------------------------------------------------------------------
__device__ __forceinline__ uint32_t smem_u32(const void* p) {
    uint32_t a;
    asm("{ .reg .u64 t; cvta.to.shared.u64 t, %1; cvt.u32.u64 %0, t; }"
        : "=r"(a) : "l"(p));
    return a;
}

__device__ __forceinline__ void ldsm_x4(uint32_t* r, uint32_t addr) {
    asm volatile("ldmatrix.sync.aligned.m8n8.x4.shared.b16 {%0,%1,%2,%3}, [%4];"
                 : "=r"(r[0]), "=r"(r[1]), "=r"(r[2]), "=r"(r[3]) : "r"(addr));
}

__device__ __forceinline__ void mma_bf16(float* d, const uint32_t* a,
                                         uint32_t b0, uint32_t b1) {
    asm volatile("mma.sync.aligned.m16n8k16.row.col.f32.bf16.bf16.f32 "
                 "{%0,%1,%2,%3}, {%4,%5,%6,%7}, {%8,%9}, {%0,%1,%2,%3};"
                 : "+f"(d[0]), "+f"(d[1]), "+f"(d[2]), "+f"(d[3])
                 : "r"(a[0]), "r"(a[1]), "r"(a[2]), "r"(a[3]),
                   "r"(b0), "r"(b1));
}

// ---------------------------------------------------------------------------
// W preconvert: split fp32 W[512,96] into bf16 hi/lo, transposed [96][512]
// ---------------------------------------------------------------------------
__global__ void wconv_kernel(const float* __restrict__ W) {
    int i = blockIdx.x * blockDim.x + threadIdx.x;
    if (i < IN_F * OUT_F) {
        int k = i / OUT_F, n = i % OUT_F;
        float w = W[i];
        __nv_bfloat16 hi = __float2bfloat16_rn(w);
        float lo = w - __bfloat162float(hi);
        g_WhiT[(size_t)n * IN_F + k] = hi;
        g_WloT[(size_t)n * IN_F + k] = __float2bfloat16_rn(lo);
    }
}

// ---------------------------------------------------------------------------
// GEMM via mma.sync bf16 split: support = X @ W
// CTA 128x96, 8 warps (4M x 2N), warp tile 32x48, K-chunk 64.
// D = Xhi*Whi + Xhi*Wlo + Xlo*Whi  (lo*lo dropped; rel err ~1e-6)
// ---------------------------------------------------------------------------
#define SMS 144   // bytes per smem row
#define A_HI_OFF 0
#define A_LO_OFF 18432         // 128*144
#define B_HI_OFF 36864
#define B_LO_OFF 50688
#define GEMM_SMEM 64512

__global__ __launch_bounds__(256, 2) void gemm_mma_kernel(
    const float* __restrict__ X, float* __restrict__ out)
{
    extern __shared__ char sm[];
    char* As_hi = sm + A_HI_OFF;
    char* As_lo = sm + A_LO_OFF;
    char* Bs_hi = sm + B_HI_OFF;
    char* Bs_lo = sm + B_LO_OFF;

    const int tid  = threadIdx.x;
    const int lane = tid & 31;
    const int wid  = tid >> 5;
    const int wm   = wid >> 1;
    const int wn   = wid & 1;
    const int ctaM = blockIdx.x * 128;

    float acc[2][6][4];
#pragma unroll
    for (int mt = 0; mt < 2; ++mt)
#pragma unroll
        for (int nt = 0; nt < 6; ++nt)
#pragma unroll
            for (int r = 0; r < 4; ++r) acc[mt][nt][r] = 0.0f;

    const uint32_t a_hi = smem_u32(As_hi);
    const uint32_t a_lo = smem_u32(As_lo);
    const uint32_t b_hi = smem_u32(Bs_hi);
    const uint32_t b_lo = smem_u32(Bs_lo);

    const int a_row = ((lane >> 3) & 1) * 8 + (lane & 7);
    const int a_kh  = lane >> 4;
    const int b_row = ((lane >> 4) & 1) * 8 + (lane & 7);
    const int b_kh  = (lane >> 3) & 1;

    for (int k0 = 0; k0 < IN_F; k0 += 64) {
#pragma unroll
        for (int j = 0; j < 8; ++j) {
            int i   = tid + j * 256;
            int row = i >> 4;
            int kg  = i & 15;
            int grow = ctaM + row;
            if (grow >= N_NODES) grow = N_NODES - 1;
            float4 v = *reinterpret_cast<const float4*>(
                X + (size_t)grow * IN_F + k0 + kg * 4);
            __nv_bfloat16 h0 = __float2bfloat16_rn(v.x);
            __nv_bfloat16 h1 = __float2bfloat16_rn(v.y);
            __nv_bfloat16 h2 = __float2bfloat16_rn(v.z);
            __nv_bfloat16 h3 = __float2bfloat16_rn(v.w);
            char* ph = As_hi + row * SMS + kg * 8;
            *reinterpret_cast<__nv_bfloat162*>(ph)     = __halves2bfloat162(h0, h1);
            *reinterpret_cast<__nv_bfloat162*>(ph + 4) = __halves2bfloat162(h2, h3);
            __nv_bfloat16 l0 = __float2bfloat16_rn(v.x - __bfloat162float(h0));
            __nv_bfloat16 l1 = __float2bfloat16_rn(v.y - __bfloat162float(h1));
            __nv_bfloat16 l2 = __float2bfloat16_rn(v.z - __bfloat162float(h2));
            __nv_bfloat16 l3 = __float2bfloat16_rn(v.w - __bfloat162float(h3));
            char* pl = As_lo + row * SMS + kg * 8;
            *reinterpret_cast<__nv_bfloat162*>(pl)     = __halves2bfloat162(l0, l1);
            *reinterpret_cast<__nv_bfloat162*>(pl + 4) = __halves2bfloat162(l2, l3);
        }
#pragma unroll
        for (int j = 0; j < 3; ++j) {
            int i   = tid + j * 256;
            int row = i >> 3;
            int kg  = i & 7;
            size_t goff = ((size_t)row * IN_F + k0) * 2 + kg * 16;
            *reinterpret_cast<uint4*>(Bs_hi + row * SMS + kg * 16) =
                *reinterpret_cast<const uint4*>(
                    reinterpret_cast<const char*>(g_WhiT) + goff);
            *reinterpret_cast<uint4*>(Bs_lo + row * SMS + kg * 16) =
                *reinterpret_cast<const uint4*>(
                    reinterpret_cast<const char*>(g_WloT) + goff);
        }
        __syncthreads();

#pragma unroll
        for (int ks = 0; ks < 4; ++ks) {
            uint32_t Ah[2][4], Al[2][4];
#pragma unroll
            for (int mt = 0; mt < 2; ++mt) {
                uint32_t off = (uint32_t)((wm * 32 + mt * 16 + a_row) * SMS
                                          + ks * 32 + a_kh * 16);
                ldsm_x4(Ah[mt], a_hi + off);
                ldsm_x4(Al[mt], a_lo + off);
            }
            uint32_t Bh[3][4], Bl[3][4];
#pragma unroll
            for (int np = 0; np < 3; ++np) {
                uint32_t off = (uint32_t)((wn * 48 + np * 16 + b_row) * SMS
                                          + ks * 32 + b_kh * 16);
                ldsm_x4(Bh[np], b_hi + off);
                ldsm_x4(Bl[np], b_lo + off);
            }
#pragma unroll
            for (int mt = 0; mt < 2; ++mt)
#pragma unroll
                for (int nt = 0; nt < 6; ++nt) {
                    uint32_t bh0 = Bh[nt >> 1][(nt & 1) * 2];
                    uint32_t bh1 = Bh[nt >> 1][(nt & 1) * 2 + 1];
                    uint32_t bl0 = Bl[nt >> 1][(nt & 1) * 2];
                    uint32_t bl1 = Bl[nt >> 1][(nt & 1) * 2 + 1];
                    mma_bf16(acc[mt][nt], Ah[mt], bh0, bh1);
                    mma_bf16(acc[mt][nt], Ah[mt], bl0, bl1);
                    mma_bf16(acc[mt][nt], Al[mt], bh0, bh1);
                }
        }
        __syncthreads();
    }

#pragma unroll
    for (int mt = 0; mt < 2; ++mt) {
        int row0 = ctaM + wm * 32 + mt * 16 + (lane >> 2);
#pragma unroll
        for (int nt = 0; nt < 6; ++nt) {
            int col = wn * 48 + nt * 8 + (lane & 3) * 2;
            if (row0 < N_NODES) {
                float2 v = make_float2(acc[mt][nt][0], acc[mt][nt][1]);
                *reinterpret_cast<float2*>(out + (size_t)row0 * OUT_F + col) = v;
            }
            int row1 = row0 + 8;
            if (row1 < N_NODES) {
                float2 v = make_float2(acc[mt][nt][2], acc[mt][nt][3]);
                *reinterpret_cast<float2*>(out + (size_t)row1 * OUT_F + col) = v;
            }
        }
    }
}

// ---------------------------------------------------------------------------
// CSR build: histogram -> scan -> fill
// ---------------------------------------------------------------------------
__global__ void zero_deg_kernel() {
    int i = blockIdx.x * blockDim.x + threadIdx.x;
    if (i < N_NODES) g_deg[i] = 0;
}

__global__ void hist_kernel(const int* __restrict__ dst) {
    int i = blockIdx.x * blockDim.x + threadIdx.x;
    if (i < N_EDGES) atomicAdd(&g_deg[dst[i]], 1);
}

__global__ __launch_bounds__(SCAN_BLK) void scan1_kernel() {
    __shared__ int sh[SCAN_BLK];
    int t = threadIdx.x;
    int gi = blockIdx.x * SCAN_BLK + t;
    int v = (gi < N_NODES) ? g_deg[gi] : 0;
    sh[t] = v;
    __syncthreads();
#pragma unroll
    for (int off = 1; off < SCAN_BLK; off <<= 1) {
        int x = (t >= off) ? sh[t - off] : 0;
        __syncthreads();
        sh[t] += x;
        __syncthreads();
    }
    if (gi < N_NODES) g_rowptr[gi] = sh[t] - v;
    if (t == SCAN_BLK - 1) g_blocksum[blockIdx.x] = sh[t];
}

__global__ __launch_bounds__(128) void scan2_kernel() {
    __shared__ int sh[128];
    int t = threadIdx.x;
    int v = (t < NBLK) ? g_blocksum[t] : 0;
    sh[t] = v;
    __syncthreads();
#pragma unroll
    for (int off = 1; off < 128; off <<= 1) {
        int x = (t >= off) ? sh[t - off] : 0;
        __syncthreads();
        sh[t] += x;
        __syncthreads();
    }
    if (t < NBLK) g_blockoff[t] = sh[t] - v;
}

__global__ void scan3_kernel() {
    int i = blockIdx.x * blockDim.x + threadIdx.x;
    if (i < N_NODES) {
        int r = g_rowptr[i] + g_blockoff[i / SCAN_BLK];
        g_rowptr[i] = r;
        g_cursor[i] = r;
    }
    if (i == 0) g_rowptr[N_NODES] = N_EDGES;
}

__global__ void fill_kernel(const int* __restrict__ src,
                            const int* __restrict__ dst,
                            const float* __restrict__ val) {
    int i = blockIdx.x * blockDim.x + threadIdx.x;
    if (i < N_EDGES) {
        int pos = atomicAdd(&g_cursor[dst[i]], 1);
        g_esrc[pos] = src[i];
        g_eval[pos] = val[i] * (1.0f - ALPHA);
    }
}

// ---------------------------------------------------------------------------
// SpMM (gather, warp-per-destination-node), fused residual + lazy ReLU
// (identical to the proven 24.5us/iter R3 configuration)
// ---------------------------------------------------------------------------
template <int RELU_IN, int RELU_OUT>
__global__ __launch_bounds__(256) void spmm_kernel(
    const float* __restrict__ cur, const float* __restrict__ sup,
    float* __restrict__ out)
{
    int warp = (blockIdx.x * 256 + threadIdx.x) >> 5;
    int lane = threadIdx.x & 31;
    if (warp >= N_NODES) return;

    int beg = g_rowptr[warp];
    int end = g_rowptr[warp + 1];

    float a0 = 0.f, a1 = 0.f, a2 = 0.f;

    int i = beg;
    for (; i + 4 <= end; i += 4) {
        int   s0 = __ldg(&g_esrc[i]),     s1 = __ldg(&g_esrc[i + 1]);
        int   s2 = __ldg(&g_esrc[i + 2]), s3 = __ldg(&g_esrc[i + 3]);
        float v0 = __ldg(&g_eval[i]),     v1 = __ldg(&g_eval[i + 1]);
        float v2 = __ldg(&g_eval[i + 2]), v3 = __ldg(&g_eval[i + 3]);
        const float* h0 = cur + (size_t)s0 * OUT_F;
        const float* h1 = cur + (size_t)s1 * OUT_F;
        const float* h2 = cur + (size_t)s2 * OUT_F;
        const float* h3 = cur + (size_t)s3 * OUT_F;
        float x0 = __ldg(h0 + lane), x1 = __ldg(h0 + lane + 32), x2 = __ldg(h0 + lane + 64);
        float y0 = __ldg(h1 + lane), y1 = __ldg(h1 + lane + 32), y2 = __ldg(h1 + lane + 64);
        float z0 = __ldg(h2 + lane), z1 = __ldg(h2 + lane + 32), z2 = __ldg(h2 + lane + 64);
        float w0 = __ldg(h3 + lane), w1 = __ldg(h3 + lane + 32), w2 = __ldg(h3 + lane + 64);
        if (RELU_IN) {
            x0 = fmaxf(x0, 0.f); x1 = fmaxf(x1, 0.f); x2 = fmaxf(x2, 0.f);
            y0 = fmaxf(y0, 0.f); y1 = fmaxf(y1, 0.f); y2 = fmaxf(y2, 0.f);
            z0 = fmaxf(z0, 0.f); z1 = fmaxf(z1, 0.f); z2 = fmaxf(z2, 0.f);
            w0 = fmaxf(w0, 0.f); w1 = fmaxf(w1, 0.f); w2 = fmaxf(w2, 0.f);
        }
        a0 = fmaf(v0, x0, a0); a1 = fmaf(v0, x1, a1); a2 = fmaf(v0, x2, a2);
        a0 = fmaf(v1, y0, a0); a1 = fmaf(v1, y1, a1); a2 = fmaf(v1, y2, a2);
        a0 = fmaf(v2, z0, a0); a1 = fmaf(v2, z1, a1); a2 = fmaf(v2, z2, a2);
        a0 = fmaf(v3, w0, a0); a1 = fmaf(v3, w1, a1); a2 = fmaf(v3, w2, a2);
    }
    for (; i < end; ++i) {
        int   s0 = __ldg(&g_esrc[i]);
        float v0 = __ldg(&g_eval[i]);
        const float* h0 = cur + (size_t)s0 * OUT_F;
        float x0 = __ldg(h0 + lane), x1 = __ldg(h0 + lane + 32), x2 = __ldg(h0 + lane + 64);
        if (RELU_IN) {
            x0 = fmaxf(x0, 0.f); x1 = fmaxf(x1, 0.f); x2 = fmaxf(x2, 0.f);
        }
        a0 = fmaf(v0, x0, a0); a1 = fmaf(v0, x1, a1); a2 = fmaf(v0, x2, a2);
    }

    const float* sp = sup + (size_t)warp * OUT_F;
    float r0 = fmaf(ALPHA, __ldg(sp + lane),      a0);
    float r1 = fmaf(ALPHA, __ldg(sp + lane + 32), a1);
    float r2 = fmaf(ALPHA, __ldg(sp + lane + 64), a2);
    if (RELU_OUT) {
        r0 = fmaxf(r0, 0.f); r1 = fmaxf(r1, 0.f); r2 = fmaxf(r2, 0.f);
    }
    float* o = out + (size_t)warp * OUT_F;
    o[lane] = r0; o[lane + 32] = r1; o[lane + 64] = r2;
}

// ---------------------------------------------------------------------------
extern "C" void kernel_launch(void* const* d_in, const int* in_sizes, int n_in,
                              void* d_out, int out_size)
{
    const float* x    = (const float*)d_in[0];
    const float* w    = (const float*)d_in[1];
    const int*   src  = (const int*)d_in[2];
    const int*   dst  = (const int*)d_in[3];
    const float* val  = (const float*)d_in[4];
    float*       out  = (float*)d_out;

    float *sup, *bufA, *bufB;
    cudaGetSymbolAddress((void**)&sup,  g_support);
    cudaGetSymbolAddress((void**)&bufA, g_bufA);
    cudaGetSymbolAddress((void**)&bufB, g_bufB);

    // Side stream + events for capture fork-join (created once; host-side
    // resources only — no device memory, identical captured work every call).
    static cudaStream_t s_csr = nullptr;
    static cudaEvent_t  ev_fork = nullptr, ev_join = nullptr;
    if (!s_csr) {
        cudaStreamCreateWithFlags(&s_csr, cudaStreamNonBlocking);
        cudaEventCreateWithFlags(&ev_fork, cudaEventDisableTiming);
        cudaEventCreateWithFlags(&ev_join, cudaEventDisableTiming);
    }

    cudaFuncSetAttribute(gemm_mma_kernel,
                         cudaFuncAttributeMaxDynamicSharedMemorySize, GEMM_SMEM);

    // ---- fork: CSR build on side stream, GEMM on main stream ----
    cudaEventRecord(ev_fork, 0);
    cudaStreamWaitEvent(s_csr, ev_fork, 0);

    // branch A (main stream): W preconvert + GEMM
    wconv_kernel<<<(IN_F * OUT_F + 255) / 256, 256>>>(w);
    gemm_mma_kernel<<<(N_NODES + 127) / 128, 256, GEMM_SMEM>>>(x, sup);

    // branch B (side stream): CSR build (dst-sorted adjacency)
    zero_deg_kernel<<<(N_NODES + 255) / 256, 256, 0, s_csr>>>();
    hist_kernel<<<(N_EDGES + 255) / 256, 256, 0, s_csr>>>(dst);
    scan1_kernel<<<NBLK, SCAN_BLK, 0, s_csr>>>();
    scan2_kernel<<<1, 128, 0, s_csr>>>();
    scan3_kernel<<<(N_NODES + 255) / 256, 256, 0, s_csr>>>();
    fill_kernel<<<(N_EDGES + 255) / 256, 256, 0, s_csr>>>(src, dst, val);

    // ---- join ----
    cudaEventRecord(ev_join, s_csr);
    cudaStreamWaitEvent(0, ev_join, 0);

    // 10 propagation iterations, warp-per-node gather SpMM (fp32 state)
    const int spmmBlocks = (N_NODES * 32 + 255) / 256;
    const float* cur = sup;
    for (int it = 0; it < ITERS; ++it) {
        float* nxt = (it == ITERS - 1) ? out : ((it & 1) ? bufB : bufA);
        if (it == 0)
            spmm_kernel<0, 0><<<spmmBlocks, 256>>>(cur, sup, nxt);
        else if (it == ITERS - 1)
            spmm_kernel<1, 1><<<spmmBlocks, 256>>>(cur, sup, nxt);
        else
            spmm_kernel<1, 0><<<spmmBlocks, 256>>>(cur, sup, nxt);
        cur = nxt;
    }
}